// round 1
// baseline (speedup 1.0000x reference)
#include <cuda_runtime.h>

typedef unsigned long long u64;

#define NL   19
#define DIM  6
#define ROWS 4          // rows per thread = 2 packed f32x2 lanes
#define TPB  256

// ---------------- packed f32x2 helpers (Blackwell sm_103a) ----------------
__device__ __forceinline__ u64 fma2(u64 a, u64 b, u64 c) {
    u64 d; asm("fma.rn.f32x2 %0, %1, %2, %3;" : "=l"(d) : "l"(a), "l"(b), "l"(c)); return d;
}
__device__ __forceinline__ u64 mul2(u64 a, u64 b) {
    u64 d; asm("mul.rn.f32x2 %0, %1, %2;" : "=l"(d) : "l"(a), "l"(b)); return d;
}
__device__ __forceinline__ u64 add2(u64 a, u64 b) {
    u64 d; asm("add.rn.f32x2 %0, %1, %2;" : "=l"(d) : "l"(a), "l"(b)); return d;
}
__device__ __forceinline__ u64 pack2(float x, float y) {
    u64 d; asm("mov.b64 %0, {%1, %2};" : "=l"(d) : "f"(x), "f"(y)); return d;
}
__device__ __forceinline__ void unpack2(u64 v, float &x, float &y) {
    asm("mov.b64 {%0, %1}, %2;" : "=f"(x), "=f"(y) : "l"(v));
}

// lrelu(x) = 0.505*x + 0.495*|x|  (== x for x>=0, 0.01*x for x<0), fully packed
#define LRELU_A 0.505f
#define LRELU_B 0.495f

__global__ void __launch_bounds__(TPB, 2)
mlp_kernel(const float* __restrict__ X,
           const float* __restrict__ Ws,
           const float* __restrict__ bs,
           const float* __restrict__ bounds,
           float* __restrict__ out,
           int B)
{
    __shared__ u64 sW[NL][DIM * DIM];   // packed {w,w}
    __shared__ u64 sB[NL][DIM];         // packed {b,b}
    __shared__ u64 sScale[DIM], sOff[DIM];

    // ---- prologue: duplicate weights into packed shared ----
    for (int i = threadIdx.x; i < NL * DIM * DIM; i += blockDim.x) {
        float w = Ws[i];
        sW[i / (DIM * DIM)][i % (DIM * DIM)] = pack2(w, w);
    }
    for (int i = threadIdx.x; i < NL * DIM; i += blockDim.x) {
        float b = bs[i];
        sB[i / DIM][i % DIM] = pack2(b, b);
    }
    if (threadIdx.x < DIM) {
        float lo = bounds[2 * threadIdx.x];
        float hi = bounds[2 * threadIdx.x + 1];
        float s  = 1.0f / (hi - lo);
        float o  = -lo * s;
        sScale[threadIdx.x] = pack2(s, s);
        sOff[threadIdx.x]   = pack2(o, o);
    }
    __syncthreads();

    long long tid  = (long long)blockIdx.x * blockDim.x + threadIdx.x;
    long long base = tid * ROWS;
    if (base >= B) return;

    const u64 CA = pack2(LRELU_A, LRELU_A);
    const u64 CB = pack2(LRELU_B, LRELU_B);

#define LIN(L, IN, OUT) do {                                                   \
    _Pragma("unroll")                                                          \
    for (int j = 0; j < DIM; j++) {                                            \
        u64 a0 = sB[(L)][j], a1 = a0;                                          \
        _Pragma("unroll")                                                      \
        for (int k = 0; k < DIM; k++) {                                        \
            u64 ww = sW[(L)][j * DIM + k];                                     \
            a0 = fma2(IN[0][k], ww, a0);                                       \
            a1 = fma2(IN[1][k], ww, a1);                                       \
        }                                                                      \
        OUT[0][j] = a0; OUT[1][j] = a1;                                        \
    } } while (0)

#define LRELU(A) do {                                                          \
    _Pragma("unroll")                                                          \
    for (int p = 0; p < 2; p++) {                                              \
        _Pragma("unroll")                                                      \
        for (int j = 0; j < DIM; j++) {                                        \
            u64 ab = A[p][j] & 0x7FFFFFFF7FFFFFFFULL;                          \
            A[p][j] = fma2(A[p][j], CA, mul2(ab, CB));                         \
        }                                                                      \
    } } while (0)

    if (base + ROWS <= B) {
        // ---------- fast path: 4 full rows, vectorized I/O ----------
        float f[ROWS * DIM];
        const float4* Xv = reinterpret_cast<const float4*>(X + base * DIM);
#pragma unroll
        for (int i = 0; i < (ROWS * DIM) / 4; i++) {
            float4 q = Xv[i];
            f[4 * i + 0] = q.x; f[4 * i + 1] = q.y;
            f[4 * i + 2] = q.z; f[4 * i + 3] = q.w;
        }

        u64 w[2][DIM], t[2][DIM], res[2][DIM];
#pragma unroll
        for (int k = 0; k < DIM; k++) {
            w[0][k] = fma2(pack2(f[k],          f[DIM + k]),     sScale[k], sOff[k]);
            w[1][k] = fma2(pack2(f[2 * DIM + k], f[3 * DIM + k]), sScale[k], sOff[k]);
        }

#pragma unroll
        for (int blk = 0; blk < 4; blk++) {
            const int i0 = blk * 4;
#pragma unroll
            for (int p = 0; p < 2; p++)
#pragma unroll
                for (int j = 0; j < DIM; j++) res[p][j] = w[p][j];

            LIN(i0 + 0, w, t); LRELU(t);
            LIN(i0 + 1, t, w); LRELU(w);
            LIN(i0 + 2, w, t); LRELU(t);
            LIN(i0 + 3, t, w);
#pragma unroll
            for (int p = 0; p < 2; p++)
#pragma unroll
                for (int j = 0; j < DIM; j++) w[p][j] = add2(w[p][j], res[p][j]);
        }
        LIN(16, w, t); LRELU(t);
        LIN(17, t, w); LRELU(w);
        LIN(18, w, t);

        float g[ROWS * DIM];
#pragma unroll
        for (int k = 0; k < DIM; k++) {
            unpack2(t[0][k], g[k],           g[DIM + k]);
            unpack2(t[1][k], g[2 * DIM + k], g[3 * DIM + k]);
        }
        float4* Ov = reinterpret_cast<float4*>(out + base * DIM);
#pragma unroll
        for (int i = 0; i < (ROWS * DIM) / 4; i++)
            Ov[i] = make_float4(g[4 * i], g[4 * i + 1], g[4 * i + 2], g[4 * i + 3]);
    } else {
        // ---------- tail path: scalar per-row (rarely taken) ----------
        const float* sWf = reinterpret_cast<const float*>(sW);      // stride 2 (packed dup)
        const float* sBf = reinterpret_cast<const float*>(sB);
        const float* sSf = reinterpret_cast<const float*>(sScale);
        const float* sOf = reinterpret_cast<const float*>(sOff);

        for (long long r = base; r < B; r++) {
            float x[DIM], y[DIM], rs[DIM];
            for (int k = 0; k < DIM; k++)
                x[k] = X[r * DIM + k] * sSf[2 * k] + sOf[2 * k];

            auto lin_s = [&](int L, const float* in, float* o) {
                for (int j = 0; j < DIM; j++) {
                    float a = sBf[(L * DIM + j) * 2];
                    for (int k = 0; k < DIM; k++)
                        a = fmaf(in[k], sWf[(L * DIM * DIM + j * DIM + k) * 2], a);
                    o[j] = a;
                }
            };
            auto lrelu_s = [&](float* v) {
                for (int j = 0; j < DIM; j++) v[j] = fmaxf(v[j], 0.01f * v[j]);
            };

            for (int blk = 0; blk < 4; blk++) {
                int i0 = blk * 4;
                for (int k = 0; k < DIM; k++) rs[k] = x[k];
                lin_s(i0 + 0, x, y); lrelu_s(y);
                lin_s(i0 + 1, y, x); lrelu_s(x);
                lin_s(i0 + 2, x, y); lrelu_s(y);
                lin_s(i0 + 3, y, x);
                for (int k = 0; k < DIM; k++) x[k] += rs[k];
            }
            lin_s(16, x, y); lrelu_s(y);
            lin_s(17, y, x); lrelu_s(x);
            lin_s(18, x, y);
            for (int k = 0; k < DIM; k++) out[r * DIM + k] = y[k];
        }
    }
#undef LIN
#undef LRELU
}

extern "C" void kernel_launch(void* const* d_in, const int* in_sizes, int n_in,
                              void* d_out, int out_size)
{
    const float* X      = (const float*)d_in[0];
    const float* Ws     = (const float*)d_in[1];
    const float* bs     = (const float*)d_in[2];
    const float* bounds = (const float*)d_in[3];
    float* out = (float*)d_out;

    int B = in_sizes[0] / DIM;
    long long tiles = ((long long)B + ROWS - 1) / ROWS;
    int blocks = (int)((tiles + TPB - 1) / TPB);

    mlp_kernel<<<blocks, TPB>>>(X, Ws, bs, bounds, out, B);
}